// round 15
// baseline (speedup 1.0000x reference)
#include <cuda_runtime.h>
#include <cstdint>
#include <math.h>

#define T_SEQ 16384
#define HDIM  512
#define G4    2048
#define NB    128     // CTAs in the recurrent kernel (<= 148, all co-resident)
#define UPB   4       // hidden units per CTA  (NB * UPB == HDIM)

// Scratch (static __device__ arrays are the allocation-guard-legal scratch path)
__device__ float g_xgates[(size_t)T_SEQ * G4];   // 128 MB precomputed input gates
// Parity-packed h broadcast ring: g_hpar[slot][unit] is h with its mantissa
// LSB forced to parity(t) = (t>>1)&1.  The LSB IS the sync tag.
__device__ __align__(16) unsigned int g_hpar[2][HDIM];

// ---------------------------------------------------------------------------
// GEMM: g_xgates[t][j] = dot(input[t,:], w_ih[j,:]) + b_ih[j]
// Block (0,0) also re-inits the h ring (LSB=1) each launch: lstm runs after
// this kernel completes (stream order), so no ordering hazard; graph replays
// stay deterministic.  2 launches/call total.
// ---------------------------------------------------------------------------
__global__ __launch_bounds__(256) void gemm_xgates_kernel(
    const float* __restrict__ A, const float* __restrict__ W,
    const float* __restrict__ bias)
{
    __shared__ float As[8][128];
    __shared__ float Ws[8][128];
    const int bm = blockIdx.y * 128;
    const int bn = blockIdx.x * 128;
    const int tid = threadIdx.x;

    if (bm == 0 && bn == 0) {           // fold ring init into the GEMM launch
        for (int i = tid; i < 2 * HDIM; i += 256)
            ((unsigned int*)g_hpar)[i] = 1u;
    }

    const int lr = tid >> 1;
    const int lc = (tid & 1) << 2;
    const int tx = tid & 15;
    const int ty = tid >> 4;

    float acc[8][8];
#pragma unroll
    for (int i = 0; i < 8; i++)
#pragma unroll
        for (int j = 0; j < 8; j++) acc[i][j] = 0.0f;

    const float* Aptr = A + (size_t)(bm + lr) * HDIM + lc;
    const float* Wptr = W + (size_t)(bn + lr) * HDIM + lc;

    for (int k0 = 0; k0 < HDIM; k0 += 8) {
        float4 av = *(const float4*)(Aptr + k0);
        float4 wv = *(const float4*)(Wptr + k0);
        __syncthreads();
        As[lc + 0][lr] = av.x; As[lc + 1][lr] = av.y;
        As[lc + 2][lr] = av.z; As[lc + 3][lr] = av.w;
        Ws[lc + 0][lr] = wv.x; Ws[lc + 1][lr] = wv.y;
        Ws[lc + 2][lr] = wv.z; Ws[lc + 3][lr] = wv.w;
        __syncthreads();
#pragma unroll
        for (int k = 0; k < 8; k++) {
            float a[8], b[8];
            *(float4*)(a)     = *(const float4*)&As[k][ty * 8];
            *(float4*)(a + 4) = *(const float4*)&As[k][ty * 8 + 4];
            *(float4*)(b)     = *(const float4*)&Ws[k][tx * 8];
            *(float4*)(b + 4) = *(const float4*)&Ws[k][tx * 8 + 4];
#pragma unroll
            for (int i = 0; i < 8; i++)
#pragma unroll
                for (int j = 0; j < 8; j++)
                    acc[i][j] = fmaf(a[i], b[j], acc[i][j]);
        }
    }

    float bb[8];
    *(float4*)(bb)     = *(const float4*)&bias[bn + tx * 8];
    *(float4*)(bb + 4) = *(const float4*)&bias[bn + tx * 8 + 4];
#pragma unroll
    for (int i = 0; i < 8; i++) {
        float* cp = g_xgates + (size_t)(bm + ty * 8 + i) * G4 + bn + tx * 8;
        float4 v0 = make_float4(acc[i][0] + bb[0], acc[i][1] + bb[1],
                                acc[i][2] + bb[2], acc[i][3] + bb[3]);
        float4 v1 = make_float4(acc[i][4] + bb[4], acc[i][5] + bb[5],
                                acc[i][6] + bb[6], acc[i][7] + bb[7]);
        *(float4*)cp       = v0;
        *(float4*)(cp + 4) = v1;
    }
}

// ---------------------------------------------------------------------------
// Recurrent persistent kernel — R8 protocol, GRANULE-STREAMING consume:
// no smem h staging, no barrier A.  Lane l's matvec slice h[16l..16l+16)
// is exactly 4 consecutive v4 granules of g_hpar; the lane polls each
// granule directly from L2 and issues its 16 FMAs the moment it lands,
// overlapping detect latency with compute.
// ---------------------------------------------------------------------------
__device__ __forceinline__ float sigmoid_fast(float x) {
    return __fdividef(1.0f, 1.0f + __expf(-x));
}
__device__ __forceinline__ float tanh_fast(float x) {
    return 1.0f - __fdividef(2.0f, __expf(2.0f * x) + 1.0f);
}
__device__ __forceinline__ void ld_relaxed_v4u(const unsigned int* p,
                                               unsigned int& a, unsigned int& b,
                                               unsigned int& c, unsigned int& d) {
    asm volatile("ld.relaxed.gpu.global.v4.b32 {%0,%1,%2,%3}, [%4];"
                 : "=r"(a), "=r"(b), "=r"(c), "=r"(d) : "l"(p) : "memory");
}
__device__ __forceinline__ void st_relaxed_u32(unsigned int* p, unsigned int v) {
    asm volatile("st.relaxed.gpu.global.b32 [%0], %1;" :: "l"(p), "r"(v) : "memory");
}

__global__ void __launch_bounds__(128, 1) lstm_rec_kernel(
    const float* __restrict__ Whh, float* __restrict__ out)
{
    const int b   = blockIdx.x;
    const int tid = threadIdx.x;
    const int w   = tid >> 5;   // warp = owned unit index (0..3)
    const int l   = tid & 31;

    // Preload W_hh rows: wt[gate][k] for unit gu = 4b+w, cols 16l..16l+15
    const int gu = b * UPB + w;
    float wt[4][16];
#pragma unroll
    for (int g = 0; g < 4; g++) {
        const float* row = Whh + (size_t)(g * HDIM + gu) * HDIM + l * 16;
#pragma unroll
        for (int kk = 0; kk < 16; kk += 4) {
            float4 v = *(const float4*)(row + kk);
            wt[g][kk] = v.x; wt[g][kk + 1] = v.y;
            wt[g][kk + 2] = v.z; wt[g][kk + 3] = v.w;
        }
    }

    float c_state = 0.0f;                          // lane 0 of each warp
    const unsigned int* hslice = &g_hpar[0][l * 16];  // lane's 4-granule slice

    for (int t = 0; t < T_SEQ; t++) {
        // xg for this warp's unit: lanes 0-3 each fetch one gate pre-activation
        // (in flight during the granule polls below)
        float xg = 0.0f;
        if (l < 4) {
            const float* xr = g_xgates + (size_t)t * G4 + l * HDIM + gu;
            asm volatile("ld.global.cs.b32 %0, [%1];" : "=f"(xg) : "l"(xr));
        }

        float a0 = 0.f, a1 = 0.f, a2 = 0.f, a3 = 0.f;
        if (t > 0) {
            const unsigned int par = ((unsigned int)(t - 1) >> 1) & 1u;
            const unsigned int* hp = hslice + (((t - 1) & 1) ? HDIM : 0);
            // Stream the lane's 4 granules: poll -> immediately FMA its 4 cols
#pragma unroll
            for (int g4 = 0; g4 < 4; g4++) {
                unsigned int v0, v1, v2, v3;
                while (true) {
                    ld_relaxed_v4u(hp + 4 * g4, v0, v1, v2, v3);
                    if ((((v0 ^ par) | (v1 ^ par) |
                          (v2 ^ par) | (v3 ^ par)) & 1u) == 0u)
                        break;
                }
                float h0 = __uint_as_float(v0), h1 = __uint_as_float(v1);
                float h2 = __uint_as_float(v2), h3 = __uint_as_float(v3);
                const int k = 4 * g4;
                a0 = fmaf(wt[0][k+0], h0, a0); a1 = fmaf(wt[1][k+0], h0, a1);
                a2 = fmaf(wt[2][k+0], h0, a2); a3 = fmaf(wt[3][k+0], h0, a3);
                a0 = fmaf(wt[0][k+1], h1, a0); a1 = fmaf(wt[1][k+1], h1, a1);
                a2 = fmaf(wt[2][k+1], h1, a2); a3 = fmaf(wt[3][k+1], h1, a3);
                a0 = fmaf(wt[0][k+2], h2, a0); a1 = fmaf(wt[1][k+2], h2, a1);
                a2 = fmaf(wt[2][k+2], h2, a2); a3 = fmaf(wt[3][k+2], h2, a3);
                a0 = fmaf(wt[0][k+3], h3, a0); a1 = fmaf(wt[1][k+3], h3, a1);
                a2 = fmaf(wt[2][k+3], h3, a2); a3 = fmaf(wt[3][k+3], h3, a3);
            }
        }
        // Full butterfly: all lanes end with the complete 4 gate sums
#pragma unroll
        for (int off = 16; off >= 1; off >>= 1) {
            a0 += __shfl_xor_sync(0xffffffffu, a0, off);
            a1 += __shfl_xor_sync(0xffffffffu, a1, off);
            a2 += __shfl_xor_sync(0xffffffffu, a2, off);
            a3 += __shfl_xor_sync(0xffffffffu, a3, off);
        }

        // Lanes 0-3 apply their gate's activation in parallel (MUFU path)
        float act = 0.0f;
        if (l < 4) {
            float pre = (l == 0 ? a0 : l == 1 ? a1 : l == 2 ? a2 : a3) + xg;
            act = (l == 2) ? tanh_fast(pre) : sigmoid_fast(pre);
        }
        float iv = __shfl_sync(0xffffffffu, act, 0);
        float fv = __shfl_sync(0xffffffffu, act, 1);
        float gv = __shfl_sync(0xffffffffu, act, 2);
        float ov = __shfl_sync(0xffffffffu, act, 3);

        if (l == 0) {
            c_state = fv * c_state + iv * gv;
            float hval = ov * tanh_fast(c_state);
            // Force mantissa LSB = parity(t); publish = the signal
            unsigned int hb = (__float_as_uint(hval) & ~1u) |
                              (((unsigned int)t >> 1) & 1u);
            st_relaxed_u32(&g_hpar[t & 1][gu], hb);
            out[(size_t)t * HDIM + gu] = __uint_as_float(hb);
        }
        __syncthreads();   // trailing barrier: re-aligns warps each step
    }
}

// ---------------------------------------------------------------------------
extern "C" void kernel_launch(void* const* d_in, const int* in_sizes, int n_in,
                              void* d_out, int out_size) {
    const float* input = (const float*)d_in[0];  // [T, H]
    const float* w_ih  = (const float*)d_in[1];  // [4H, H]
    const float* w_hh  = (const float*)d_in[2];  // [4H, H]
    const float* b_ih  = (const float*)d_in[3];  // [4H]
    float* out = (float*)d_out;                  // [T, H]
    (void)in_sizes; (void)n_in; (void)out_size;

    dim3 gg(G4 / 128, T_SEQ / 128);              // 16 x 128 blocks
    gemm_xgates_kernel<<<gg, 256>>>(input, w_ih, b_ih);

    lstm_rec_kernel<<<NB, 128>>>(w_hh, out);
}

// round 16
// speedup vs baseline: 8.4857x; 8.4857x over previous
#include <cuda_runtime.h>
#include <cstdint>
#include <math.h>

#define T_SEQ 16384
#define HDIM  512
#define G4    2048
#define NB    128     // CTAs in the recurrent kernel (<= 148, all co-resident)
#define UPB   4       // hidden units per CTA  (NB * UPB == HDIM)

// Scratch (static __device__ arrays are the allocation-guard-legal scratch path)
__device__ float g_xgates[(size_t)T_SEQ * G4];   // 128 MB precomputed input gates
// Parity-packed h broadcast ring: g_hpar[slot][unit] is h with its mantissa
// LSB forced to parity((t)) = (t>>1)&1.  The LSB IS the sync tag: a single
// 4B morally-strong store publishes value+phase atomically, and consumers
// poll 4 units with ONE 16B relaxed load (halves the L2 poll request storm).
__device__ __align__(16) unsigned int g_hpar[2][HDIM];

// ---------------------------------------------------------------------------
// Prologue: init ring with LSB=1 (never matches the first expected parity 0)
// ---------------------------------------------------------------------------
__global__ void init_ring_kernel() {
    int i = blockIdx.x * blockDim.x + threadIdx.x;
    if (i < 2 * HDIM) ((unsigned int*)g_hpar)[i] = 1u;  // denormal, LSB=1
}

// ---------------------------------------------------------------------------
// GEMM: g_xgates[t][j] = dot(input[t,:], w_ih[j,:]) + b_ih[j]
// 128x128 block tile, BK=8, 256 threads, 8x8 per-thread tile. Full fp32 FMA.
// ---------------------------------------------------------------------------
__global__ __launch_bounds__(256) void gemm_xgates_kernel(
    const float* __restrict__ A, const float* __restrict__ W,
    const float* __restrict__ bias)
{
    __shared__ float As[8][128];
    __shared__ float Ws[8][128];
    const int bm = blockIdx.y * 128;   // along T
    const int bn = blockIdx.x * 128;   // along 4H
    const int tid = threadIdx.x;
    const int lr = tid >> 1;           // 0..127 tile row for loads
    const int lc = (tid & 1) << 2;     // 0 or 4 (float4 column)
    const int tx = tid & 15;
    const int ty = tid >> 4;

    float acc[8][8];
#pragma unroll
    for (int i = 0; i < 8; i++)
#pragma unroll
        for (int j = 0; j < 8; j++) acc[i][j] = 0.0f;

    const float* Aptr = A + (size_t)(bm + lr) * HDIM + lc;
    const float* Wptr = W + (size_t)(bn + lr) * HDIM + lc;

    for (int k0 = 0; k0 < HDIM; k0 += 8) {
        float4 av = *(const float4*)(Aptr + k0);
        float4 wv = *(const float4*)(Wptr + k0);
        __syncthreads();   // guard previous iteration's smem reads
        As[lc + 0][lr] = av.x; As[lc + 1][lr] = av.y;
        As[lc + 2][lr] = av.z; As[lc + 3][lr] = av.w;
        Ws[lc + 0][lr] = wv.x; Ws[lc + 1][lr] = wv.y;
        Ws[lc + 2][lr] = wv.z; Ws[lc + 3][lr] = wv.w;
        __syncthreads();
#pragma unroll
        for (int k = 0; k < 8; k++) {
            float a[8], b[8];
            *(float4*)(a)     = *(const float4*)&As[k][ty * 8];
            *(float4*)(a + 4) = *(const float4*)&As[k][ty * 8 + 4];
            *(float4*)(b)     = *(const float4*)&Ws[k][tx * 8];
            *(float4*)(b + 4) = *(const float4*)&Ws[k][tx * 8 + 4];
#pragma unroll
            for (int i = 0; i < 8; i++)
#pragma unroll
                for (int j = 0; j < 8; j++)
                    acc[i][j] = fmaf(a[i], b[j], acc[i][j]);
        }
    }

    float bb[8];
    *(float4*)(bb)     = *(const float4*)&bias[bn + tx * 8];
    *(float4*)(bb + 4) = *(const float4*)&bias[bn + tx * 8 + 4];
#pragma unroll
    for (int i = 0; i < 8; i++) {
        float* cp = g_xgates + (size_t)(bm + ty * 8 + i) * G4 + bn + tx * 8;
        float4 v0 = make_float4(acc[i][0] + bb[0], acc[i][1] + bb[1],
                                acc[i][2] + bb[2], acc[i][3] + bb[3]);
        float4 v1 = make_float4(acc[i][4] + bb[4], acc[i][5] + bb[5],
                                acc[i][6] + bb[6], acc[i][7] + bb[7]);
        *(float4*)cp       = v0;
        *(float4*)(cp + 4) = v1;
    }
}

// ---------------------------------------------------------------------------
// Recurrent persistent kernel — the verified-best configuration (R8, 21.9ms):
// R6/R7 skeleton (2 barriers/step, single smem hs buffer, MUFU activations,
// xg pipelined one step ahead) + parity-packed 4B publishes + single 16B
// relaxed polls.  Every cross-SM access is morally strong at gpu scope.
// ---------------------------------------------------------------------------
// MUFU-based activations. End-to-end validated: rel_err 4.4e-7.
__device__ __forceinline__ float sigmoid_fast(float x) {
    return __fdividef(1.0f, 1.0f + __expf(-x));
}
__device__ __forceinline__ float tanh_fast(float x) {
    return 1.0f - __fdividef(2.0f, __expf(2.0f * x) + 1.0f);
}

// morally strong ops at gpu scope
__device__ __forceinline__ void ld_relaxed_v4u(const unsigned int* p,
                                               unsigned int& a, unsigned int& b,
                                               unsigned int& c, unsigned int& d) {
    asm volatile("ld.relaxed.gpu.global.v4.b32 {%0,%1,%2,%3}, [%4];"
                 : "=r"(a), "=r"(b), "=r"(c), "=r"(d) : "l"(p) : "memory");
}
__device__ __forceinline__ void st_relaxed_u32(unsigned int* p, unsigned int v) {
    asm volatile("st.relaxed.gpu.global.b32 [%0], %1;" :: "l"(p), "r"(v) : "memory");
}

// pad every 16-float group by 4 -> conflict-free LDS.128 at stride 20
#define PADIDX(i) ((i) + (((i) >> 4) << 2))

__global__ void __launch_bounds__(128, 1) lstm_rec_kernel(
    const float* __restrict__ Whh, float* __restrict__ out)
{
    const int b   = blockIdx.x;
    const int tid = threadIdx.x;
    const int w   = tid >> 5;   // warp = owned unit index (0..3)
    const int l   = tid & 31;

    __shared__ float hs[640];   // 512 + padding

    // Preload W_hh rows: wt[gate][k] for unit gu = 4b+w, cols 16l..16l+15
    const int gu = b * UPB + w;
    float wt[4][16];
#pragma unroll
    for (int g = 0; g < 4; g++) {
        const float* row = Whh + (size_t)(g * HDIM + gu) * HDIM + l * 16;
#pragma unroll
        for (int kk = 0; kk < 16; kk += 4) {
            float4 v = *(const float4*)(row + kk);
            wt[g][kk] = v.x; wt[g][kk + 1] = v.y;
            wt[g][kk + 2] = v.z; wt[g][kk + 3] = v.w;
        }
    }

    for (int i = tid; i < 640; i += 128) hs[i] = 0.0f;  // h_{-1} = 0
    float c_state = 0.0f;                               // lane 0 of each warp
    __syncthreads();

    // Software-pipelined xg: lanes 0-3 hold one gate pre-activation each,
    // loaded one full step ahead of use.
    const bool xlane = (l < 4);
    const float* xbase = g_xgates + (size_t)l * HDIM + gu;  // valid for l<4
    float xg_cur = 0.0f;
    if (xlane) {
        asm volatile("ld.global.cs.b32 %0, [%1];" : "=f"(xg_cur) : "l"(xbase));
    }

    for (int t = 0; t < T_SEQ; t++) {
        // Issue next step's xg load immediately (covered by poll + compute)
        float xg_nxt = 0.0f;
        if (xlane) {
            const float* xr = xbase + (size_t)((t + 1 < T_SEQ) ? t + 1 : t) * G4;
            asm volatile("ld.global.cs.b32 %0, [%1];" : "=f"(xg_nxt) : "l"(xr));
        }

        if (t > 0) {
            // Poll own 4 units of h_{t-1}: ONE 16B relaxed load per iteration.
            // Expected phase parity of step t-1 = ((t-1)>>1)&1 in each LSB.
            const unsigned int* hp = &g_hpar[(t - 1) & 1][tid * 4];
            const unsigned int par = ((unsigned int)(t - 1) >> 1) & 1u;
            unsigned int v0, v1, v2, v3;
            while (true) {
                ld_relaxed_v4u(hp, v0, v1, v2, v3);
                if (((v0 ^ par) & 1u) == 0u && ((v1 ^ par) & 1u) == 0u &&
                    ((v2 ^ par) & 1u) == 0u && ((v3 ^ par) & 1u) == 0u)
                    break;
            }
            float4 hv = make_float4(__uint_as_float(v0), __uint_as_float(v1),
                                    __uint_as_float(v2), __uint_as_float(v3));
            *(float4*)&hs[PADIDX(tid * 4)] = hv;
            __syncthreads();   // barrier A: all 512 h values staged
        }

        // Matvec: 4 gate rows x 16 cols per lane
        float hv16[16];
        const float* hrow = &hs[20 * l];
#pragma unroll
        for (int kk = 0; kk < 16; kk += 4)
            *(float4*)(hv16 + kk) = *(const float4*)(hrow + kk);

        float a0 = 0.f, a1 = 0.f, a2 = 0.f, a3 = 0.f;
#pragma unroll
        for (int kk = 0; kk < 16; kk++) {
            a0 = fmaf(wt[0][kk], hv16[kk], a0);
            a1 = fmaf(wt[1][kk], hv16[kk], a1);
            a2 = fmaf(wt[2][kk], hv16[kk], a2);
            a3 = fmaf(wt[3][kk], hv16[kk], a3);
        }
        // Full butterfly: all lanes end with the complete 4 gate sums
#pragma unroll
        for (int off = 16; off >= 1; off >>= 1) {
            a0 += __shfl_xor_sync(0xffffffffu, a0, off);
            a1 += __shfl_xor_sync(0xffffffffu, a1, off);
            a2 += __shfl_xor_sync(0xffffffffu, a2, off);
            a3 += __shfl_xor_sync(0xffffffffu, a3, off);
        }

        // Lanes 0-3 apply their gate's activation in parallel (MUFU path)
        float act = 0.0f;
        if (xlane) {
            float pre = (l == 0 ? a0 : l == 1 ? a1 : l == 2 ? a2 : a3) + xg_cur;
            act = (l == 2) ? tanh_fast(pre) : sigmoid_fast(pre);
        }
        float iv = __shfl_sync(0xffffffffu, act, 0);
        float fv = __shfl_sync(0xffffffffu, act, 1);
        float gv = __shfl_sync(0xffffffffu, act, 2);
        float ov = __shfl_sync(0xffffffffu, act, 3);

        if (l == 0) {
            c_state = fv * c_state + iv * gv;
            float hval = ov * tanh_fast(c_state);
            // Force mantissa LSB = parity(t); |perturbation| <= 2^-24 rel.
            unsigned int hb = (__float_as_uint(hval) & ~1u) |
                              (((unsigned int)t >> 1) & 1u);
            float hpub = __uint_as_float(hb);
            st_relaxed_u32(&g_hpar[t & 1][gu], hb);   // 4B publish = the signal
            out[(size_t)t * HDIM + gu] = hpub;        // consistent trajectory
        }
        xg_cur = xg_nxt;
        __syncthreads();   // trailing barrier: re-aligns warps each step
    }
}

// ---------------------------------------------------------------------------
extern "C" void kernel_launch(void* const* d_in, const int* in_sizes, int n_in,
                              void* d_out, int out_size) {
    const float* input = (const float*)d_in[0];  // [T, H]
    const float* w_ih  = (const float*)d_in[1];  // [4H, H]
    const float* w_hh  = (const float*)d_in[2];  // [4H, H]
    const float* b_ih  = (const float*)d_in[3];  // [4H]
    float* out = (float*)d_out;                  // [T, H]
    (void)in_sizes; (void)n_in; (void)out_size;

    init_ring_kernel<<<4, 256>>>();

    dim3 gg(G4 / 128, T_SEQ / 128);              // 16 x 128 blocks
    gemm_xgates_kernel<<<gg, 256>>>(input, w_ih, b_ih);

    lstm_rec_kernel<<<NB, 128>>>(w_hh, out);
}

// round 17
// speedup vs baseline: 9.1015x; 1.0726x over previous
#include <cuda_runtime.h>
#include <cstdint>
#include <math.h>

#define T_SEQ 16384
#define HDIM  512
#define G4    2048
#define NB    128    // recurrence CTAs (1 unit-group per CTA)
#define NG    16     // GEMM producer CTAs
#define UPB   4      // hidden units per recurrence CTA

// Scratch (static __device__ arrays are the allocation-guard-legal scratch path)
// x_gates doubles as its own readiness flag array: prologue zeroes it (LSB=0 =
// not ready); the in-kernel GEMM publishes every value with mantissa LSB=1.
__device__ __align__(16) unsigned int g_xgates_u[(size_t)T_SEQ * G4];
// Parity-packed h broadcast ring (R8 protocol, unchanged).
__device__ __align__(16) unsigned int g_hpar[2][HDIM];

// ---------------------------------------------------------------------------
// Prologue: clear x_gates readiness (zeros) + init h ring (LSB=1)
// ---------------------------------------------------------------------------
__global__ void prologue_kernel() {
    const size_t n4 = (size_t)T_SEQ * G4 / 4;
    uint4* p = (uint4*)g_xgates_u;
    const size_t stride = (size_t)gridDim.x * blockDim.x;
    for (size_t i = blockIdx.x * (size_t)blockDim.x + threadIdx.x;
         i < n4; i += stride)
        p[i] = make_uint4(0u, 0u, 0u, 0u);
    size_t j = blockIdx.x * (size_t)blockDim.x + threadIdx.x;
    if (j < 2 * HDIM) ((unsigned int*)g_hpar)[j] = 1u;
}

// ---------------------------------------------------------------------------
// MUFU activations (validated: rel_err 4.4e-7) + morally strong gpu-scope ops
// ---------------------------------------------------------------------------
__device__ __forceinline__ float sigmoid_fast(float x) {
    return __fdividef(1.0f, 1.0f + __expf(-x));
}
__device__ __forceinline__ float tanh_fast(float x) {
    return 1.0f - __fdividef(2.0f, __expf(2.0f * x) + 1.0f);
}
__device__ __forceinline__ void ld_relaxed_v4u(const unsigned int* p,
                                               unsigned int& a, unsigned int& b,
                                               unsigned int& c, unsigned int& d) {
    asm volatile("ld.relaxed.gpu.global.v4.b32 {%0,%1,%2,%3}, [%4];"
                 : "=r"(a), "=r"(b), "=r"(c), "=r"(d) : "l"(p) : "memory");
}
__device__ __forceinline__ void st_relaxed_v4u(unsigned int* p,
                                               unsigned int a, unsigned int b,
                                               unsigned int c, unsigned int d) {
    asm volatile("st.relaxed.gpu.global.v4.b32 [%0], {%1,%2,%3,%4};"
                 :: "l"(p), "r"(a), "r"(b), "r"(c), "r"(d) : "memory");
}
__device__ __forceinline__ void ld_relaxed_u32(unsigned int& v,
                                               const unsigned int* p) {
    asm volatile("ld.relaxed.gpu.global.b32 %0, [%1];"
                 : "=r"(v) : "l"(p) : "memory");
}
__device__ __forceinline__ void st_relaxed_u32(unsigned int* p, unsigned int v) {
    asm volatile("st.relaxed.gpu.global.b32 [%0], %1;" :: "l"(p), "r"(v) : "memory");
}

// pad every 16-float group by 4 -> conflict-free LDS.128 at stride 20
#define PADIDX(i) ((i) + (((i) >> 4) << 2))

// ---------------------------------------------------------------------------
// Fused kernel: blocks 0..NB-1 = R8 recurrence (path byte-equivalent except
// xg loads are relaxed.gpu with an LSB readiness check); blocks NB..NB+NG-1 =
// GEMM producer over a t-major tile worklist (128t x 64g tiles, BK=8).
// All 144 CTAs co-resident (<=148 SMs, 1 CTA/SM): consumers may spin on
// producers, never the reverse -> deadlock-free.
// ---------------------------------------------------------------------------
__global__ void __launch_bounds__(128, 1) lstm_fused_kernel(
    const float* __restrict__ input, const float* __restrict__ Wih,
    const float* __restrict__ bias,  const float* __restrict__ Whh,
    float* __restrict__ out)
{
    __shared__ float sbuf[1536];
    const int tid = threadIdx.x;

    if (blockIdx.x >= NB) {
        // =================== GEMM producer path ===================
        const int g = blockIdx.x - NB;
        float (*As)[128] = (float(*)[128])sbuf;          // 8 x 128
        float (*Ws)[64]  = (float(*)[64])(sbuf + 1024);  // 8 x 64
        const int tx = tid & 7;     // 8 col-groups of 8
        const int ty = tid >> 3;    // 16 row-groups of 8
        const int wr = tid >> 1;    // W row 0..63
        const int wc = (tid & 1) * 4;

        for (int idx = g; idx < (T_SEQ / 128) * (G4 / 64); idx += NG) {
            const int bm = (idx >> 5) * 128;   // t-major: early steps first
            const int bn = (idx & 31) * 64;

            float acc[8][8];
#pragma unroll
            for (int i = 0; i < 8; i++)
#pragma unroll
                for (int j = 0; j < 8; j++) acc[i][j] = 0.0f;

            const float* Aptr = input + (size_t)(bm + tid) * HDIM;
            const float* Wptr = Wih + (size_t)(bn + wr) * HDIM + wc;

            for (int k0 = 0; k0 < HDIM; k0 += 8) {
                float4 a0 = *(const float4*)(Aptr + k0);
                float4 a1 = *(const float4*)(Aptr + k0 + 4);
                float4 wv = *(const float4*)(Wptr + k0);
                __syncthreads();
                As[0][tid] = a0.x; As[1][tid] = a0.y;
                As[2][tid] = a0.z; As[3][tid] = a0.w;
                As[4][tid] = a1.x; As[5][tid] = a1.y;
                As[6][tid] = a1.z; As[7][tid] = a1.w;
                Ws[wc + 0][wr] = wv.x; Ws[wc + 1][wr] = wv.y;
                Ws[wc + 2][wr] = wv.z; Ws[wc + 3][wr] = wv.w;
                __syncthreads();
#pragma unroll
                for (int k = 0; k < 8; k++) {
                    float a[8], bvec[8];
                    *(float4*)(a)        = *(const float4*)&As[k][ty * 8];
                    *(float4*)(a + 4)    = *(const float4*)&As[k][ty * 8 + 4];
                    *(float4*)(bvec)     = *(const float4*)&Ws[k][tx * 8];
                    *(float4*)(bvec + 4) = *(const float4*)&Ws[k][tx * 8 + 4];
#pragma unroll
                    for (int i = 0; i < 8; i++)
#pragma unroll
                        for (int j = 0; j < 8; j++)
                            acc[i][j] = fmaf(a[i], bvec[j], acc[i][j]);
                }
            }

            float bb[8];
            *(float4*)(bb)     = *(const float4*)&bias[bn + tx * 8];
            *(float4*)(bb + 4) = *(const float4*)&bias[bn + tx * 8 + 4];
#pragma unroll
            for (int i = 0; i < 8; i++) {
                unsigned int* cp = g_xgates_u +
                    (size_t)(bm + ty * 8 + i) * G4 + bn + tx * 8;
                // Publish with mantissa LSB=1: the readiness flag.
                st_relaxed_v4u(cp,
                    __float_as_uint(acc[i][0] + bb[0]) | 1u,
                    __float_as_uint(acc[i][1] + bb[1]) | 1u,
                    __float_as_uint(acc[i][2] + bb[2]) | 1u,
                    __float_as_uint(acc[i][3] + bb[3]) | 1u);
                st_relaxed_v4u(cp + 4,
                    __float_as_uint(acc[i][4] + bb[4]) | 1u,
                    __float_as_uint(acc[i][5] + bb[5]) | 1u,
                    __float_as_uint(acc[i][6] + bb[6]) | 1u,
                    __float_as_uint(acc[i][7] + bb[7]) | 1u);
            }
        }
        return;
    }

    // =================== Recurrence path (R8, xg via LSB-checked relaxed) ===
    const int b = blockIdx.x;
    const int w = tid >> 5;     // warp = owned unit index (0..3)
    const int l = tid & 31;
    float* hs = sbuf;           // 640 floats used

    const int gu = b * UPB + w;
    float wt[4][16];
#pragma unroll
    for (int g = 0; g < 4; g++) {
        const float* row = Whh + (size_t)(g * HDIM + gu) * HDIM + l * 16;
#pragma unroll
        for (int kk = 0; kk < 16; kk += 4) {
            float4 v = *(const float4*)(row + kk);
            wt[g][kk] = v.x; wt[g][kk + 1] = v.y;
            wt[g][kk + 2] = v.z; wt[g][kk + 3] = v.w;
        }
    }

    for (int i = tid; i < 640; i += 128) hs[i] = 0.0f;  // h_{-1} = 0
    float c_state = 0.0f;                               // lane 0 of each warp
    __syncthreads();

    // xg pipeline (one step ahead).  Values carry their own LSB readiness.
    const bool xlane = (l < 4);
    const unsigned int* xbase = g_xgates_u + (size_t)l * HDIM + gu;  // l<4
    unsigned int xg_cur_u = 0u;
    if (xlane) ld_relaxed_u32(xg_cur_u, xbase);   // row 0 (may be not-ready)

    for (int t = 0; t < T_SEQ; t++) {
        unsigned int xg_nxt_u = 0u;
        if (xlane) {
            const unsigned int* xr =
                xbase + (size_t)((t + 1 < T_SEQ) ? t + 1 : t) * G4;
            ld_relaxed_u32(xg_nxt_u, xr);
        }

        if (t > 0) {
            // Poll own 4 units of h_{t-1}: ONE 16B relaxed load per iteration.
            const unsigned int* hp = &g_hpar[(t - 1) & 1][tid * 4];
            const unsigned int par = ((unsigned int)(t - 1) >> 1) & 1u;
            unsigned int v0, v1, v2, v3;
            while (true) {
                ld_relaxed_v4u(hp, v0, v1, v2, v3);
                if (((v0 ^ par) & 1u) == 0u && ((v1 ^ par) & 1u) == 0u &&
                    ((v2 ^ par) & 1u) == 0u && ((v3 ^ par) & 1u) == 0u)
                    break;
            }
            float4 hv = make_float4(__uint_as_float(v0), __uint_as_float(v1),
                                    __uint_as_float(v2), __uint_as_float(v3));
            *(float4*)&hs[PADIDX(tid * 4)] = hv;
            __syncthreads();   // barrier A: all 512 h values staged
        }

        // Matvec: 4 gate rows x 16 cols per lane
        float hv16[16];
        const float* hrow = &hs[20 * l];
#pragma unroll
        for (int kk = 0; kk < 16; kk += 4)
            *(float4*)(hv16 + kk) = *(const float4*)(hrow + kk);

        float a0 = 0.f, a1 = 0.f, a2 = 0.f, a3 = 0.f;
#pragma unroll
        for (int kk = 0; kk < 16; kk++) {
            a0 = fmaf(wt[0][kk], hv16[kk], a0);
            a1 = fmaf(wt[1][kk], hv16[kk], a1);
            a2 = fmaf(wt[2][kk], hv16[kk], a2);
            a3 = fmaf(wt[3][kk], hv16[kk], a3);
        }
#pragma unroll
        for (int off = 16; off >= 1; off >>= 1) {
            a0 += __shfl_xor_sync(0xffffffffu, a0, off);
            a1 += __shfl_xor_sync(0xffffffffu, a1, off);
            a2 += __shfl_xor_sync(0xffffffffu, a2, off);
            a3 += __shfl_xor_sync(0xffffffffu, a3, off);
        }

        // Lanes 0-3: ensure xg ready (LSB=1), then activation (MUFU path)
        float act = 0.0f;
        if (xlane) {
            if ((xg_cur_u & 1u) == 0u) {
                const unsigned int* xr_cur = xbase + (size_t)t * G4;
                do { ld_relaxed_u32(xg_cur_u, xr_cur); }
                while ((xg_cur_u & 1u) == 0u);
            }
            float pre = (l == 0 ? a0 : l == 1 ? a1 : l == 2 ? a2 : a3) +
                        __uint_as_float(xg_cur_u);
            act = (l == 2) ? tanh_fast(pre) : sigmoid_fast(pre);
        }
        float iv = __shfl_sync(0xffffffffu, act, 0);
        float fv = __shfl_sync(0xffffffffu, act, 1);
        float gv = __shfl_sync(0xffffffffu, act, 2);
        float ov = __shfl_sync(0xffffffffu, act, 3);

        if (l == 0) {
            c_state = fv * c_state + iv * gv;
            float hval = ov * tanh_fast(c_state);
            unsigned int hb = (__float_as_uint(hval) & ~1u) |
                              (((unsigned int)t >> 1) & 1u);
            st_relaxed_u32(&g_hpar[t & 1][gu], hb);   // 4B publish = the signal
            out[(size_t)t * HDIM + gu] = __uint_as_float(hb);
        }
        xg_cur_u = xg_nxt_u;
        __syncthreads();   // trailing barrier: re-aligns warps each step
    }
}

// ---------------------------------------------------------------------------
extern "C" void kernel_launch(void* const* d_in, const int* in_sizes, int n_in,
                              void* d_out, int out_size) {
    const float* input = (const float*)d_in[0];  // [T, H]
    const float* w_ih  = (const float*)d_in[1];  // [4H, H]
    const float* w_hh  = (const float*)d_in[2];  // [4H, H]
    const float* b_ih  = (const float*)d_in[3];  // [4H]
    float* out = (float*)d_out;                  // [T, H]
    (void)in_sizes; (void)n_in; (void)out_size;

    prologue_kernel<<<4096, 256>>>();            // ~30us: clear flags + ring

    lstm_fused_kernel<<<NB + NG, 128>>>(input, w_ih, b_ih, w_hh, out);
}